// round 16
// baseline (speedup 1.0000x reference)
#include <cuda_runtime.h>
#include <cuda_bf16.h>
#include <cstdint>

// EdgeConvE: out[v,h] = sum_w A[v,w] * relu(S[v,h] + T[w,h] + sum_e E[v,w,e]*We[e,h])
// N=1024, F=32, E_ATTR=8, H_OUT=64.
// R14: ONE fused kernel = inline prep (4 v/block) + soft global barrier +
// R8 main loop (byte-identical) + last-block combine. Kills ~7us of launch
// floors. Residency proof: launch_bounds(256,2) => 2 CTA/SM => 296 slots >= 257.

#define N_NODES 1024
#define F_NODE  32
#define E_ATTR  8
#define H_OUT   64
#define NMAIN   256    // main blocks; block NMAIN is the combine block

__device__ __forceinline__ uint32_t to_tf32(float f) {
    uint32_t u; asm("cvt.rna.tf32.f32 %0, %1;" : "=r"(u) : "f"(f)); return u;
}

// ---------- scratch ----------
__device__ float  g_S [N_NODES * H_OUT];             // 256 KB
__device__ float4 g_Tf[(N_NODES / 16) * 8 * 32];     // 256 KB: T in MMA-C frag layout
__device__ float  g_part[2][N_NODES * H_OUT];        // 512 KB
__device__ int    g_prep = 0;                        // prep barrier counter
__device__ int    g_done = 0;                        // main-done counter

// ---------- the single fused kernel ----------
// Grid 257 x 256 threads. Blocks 0..255: prep slice -> barrier -> R8 main loop.
// Block 256: spin for done, combine halves, reset counters.
__global__ void __launch_bounds__(256, 2)
edge_fused(const float* __restrict__ E, const int* __restrict__ A,
           const float* __restrict__ W, const float* __restrict__ X,
           const float* __restrict__ bias, float* __restrict__ out) {
    const int bid = blockIdx.x;
    const int tid = threadIdx.x;

    // ================= combine block =================
    if (bid == NMAIN) {
        if (tid == 0) {
            while (atomicAdd(&g_done, 0) < NMAIN) { }
        }
        __syncthreads();
        __threadfence();   // acquire: make main blocks' partials visible
        const float4* p0 = (const float4*)g_part[0];
        const float4* p1 = (const float4*)g_part[1];
        float4* o4 = (float4*)out;
        for (int i = tid; i < (N_NODES * H_OUT) / 4; i += 256) {
            float4 u = p0[i], w = p1[i];
            o4[i] = make_float4(u.x + w.x, u.y + w.y, u.z + w.z, u.w + w.w);
        }
        __threadfence();
        __syncthreads();
        if (tid == 0) { g_done = 0; g_prep = 0; }   // reset for next replay
        return;
    }

    // ================= prep phase: S, T, Tf for v = bid*4 + vl =================
    {
        const int h  = tid & 63;
        const int vl = tid >> 6;
        const int v  = bid * 4 + vl;
        float s = bias[h], t = 0.0f;
#pragma unroll
        for (int f = 0; f < F_NODE; f++) {
            float x  = X[v * F_NODE + f];            // L1 broadcast within h-group
            float wv = W[f * H_OUT + h];             // coalesced, L1-resident
            float wd = W[(f + F_NODE) * H_OUT + h];
            s = fmaf(x, wv - wd, s);
            t = fmaf(x, wd, t);
        }
        g_S[v * H_OUT + h] = s;
        // scatter T into MMA-C frag layout (matches main-loop read mapping):
        const int wt   = v >> 4;
        const int gid  = v & 7;
        const int rs   = (v >> 3) & 1;
        const int t4   = (h >> 1) & 3;
        const int j    = h >> 3;
        const int elem = (h & 1) + 2 * rs;
        reinterpret_cast<float*>(g_Tf)[(((wt * 8 + j) * 32) + gid * 4 + t4) * 4 + elem] = t;
    }

    // ================= soft global barrier (256 resident main blocks) ========
    __threadfence();
    __syncthreads();
    if (tid == 0) {
        atomicAdd(&g_prep, 1);
        while (atomicAdd(&g_prep, 0) < NMAIN) { }
    }
    __syncthreads();
    __threadfence();   // acquire: all blocks' S/Tf visible

    // ================= R8 main loop (unchanged) =================
    const int vg   = bid >> 1;
    const int half = bid & 1;
    const int warp = tid >> 5;
    const int lane = tid & 31;
    const int gid  = lane >> 2;            // 0..7
    const int t4   = lane & 3;             // 0..3
    const int v    = vg * 8 + warp;

    // B frags (We in tf32), permuted-K rows 2t4 and 2t4+1
    uint32_t bf0[8], bf1[8];
#pragma unroll
    for (int j = 0; j < 8; j++) {
        bf0[j] = to_tf32(W[(2 * F_NODE + 2 * t4)     * H_OUT + j * 8 + gid]);
        bf1[j] = to_tf32(W[(2 * F_NODE + 2 * t4 + 1) * H_OUT + j * 8 + gid]);
    }
    // S pairs for this lane's h columns
    float2 sj[8];
#pragma unroll
    for (int j = 0; j < 8; j++)
        sj[j] = *(const float2*)&g_S[v * H_OUT + j * 8 + 2 * t4];

    float acc0[8], acc1[8];
#pragma unroll
    for (int j = 0; j < 8; j++) { acc0[j] = 0.0f; acc1[j] = 0.0f; }

    const float* __restrict__ Ev = E + (size_t)v * (N_NODES * E_ATTR);
    const int*   __restrict__ Av = A + v * N_NODES;
    const float4* __restrict__ Tf = g_Tf;

    const int wt0 = half * 32;
#pragma unroll 2
    for (int wt = wt0; wt < wt0 + 32; wt++) {
        const int r0 = wt * 16 + gid;
        const int r1 = r0 + 8;
        // E A-frag, permuted K: one contiguous LDG.64 per row
        float2 e0 = *(const float2*)&Ev[r0 * E_ATTR + 2 * t4];
        float2 e1 = *(const float2*)&Ev[r1 * E_ATTR + 2 * t4];
        uint32_t a0 = to_tf32(e0.x);
        uint32_t a2 = to_tf32(e0.y);
        uint32_t a1 = to_tf32(e1.x);
        uint32_t a3 = to_tf32(e1.y);
        float aF0 = (float)Av[r0];
        float aF1 = (float)Av[r1];
#pragma unroll
        for (int j = 0; j < 8; j++) {
            float4 c = Tf[(wt * 8 + j) * 32 + lane];   // coalesced 512B/warp
            float c0 = c.x + sj[j].x;
            float c1 = c.y + sj[j].y;
            float c2 = c.z + sj[j].x;
            float c3 = c.w + sj[j].y;
            float d0, d1, d2, d3;
            asm("mma.sync.aligned.m16n8k8.row.col.f32.tf32.tf32.f32 "
                "{%0,%1,%2,%3}, {%4,%5,%6,%7}, {%8,%9}, {%10,%11,%12,%13};"
                : "=f"(d0), "=f"(d1), "=f"(d2), "=f"(d3)
                : "r"(a0), "r"(a1), "r"(a2), "r"(a3),
                  "r"(bf0[j]), "r"(bf1[j]),
                  "f"(c0), "f"(c1), "f"(c2), "f"(c3));
            d0 = fmaxf(d0, 0.0f);
            d1 = fmaxf(d1, 0.0f);
            d2 = fmaxf(d2, 0.0f);
            d3 = fmaxf(d3, 0.0f);
            acc0[j] = fmaf(aF0, d0, acc0[j]);
            acc0[j] = fmaf(aF1, d2, acc0[j]);
            acc1[j] = fmaf(aF0, d1, acc1[j]);
            acc1[j] = fmaf(aF1, d3, acc1[j]);
        }
    }

    // reduce across the 8 row-groups (xor over gid bits: lanes 4,8,16)
#pragma unroll
    for (int j = 0; j < 8; j++) {
        float a = acc0[j], bq = acc1[j];
        a  += __shfl_xor_sync(0xffffffffu, a, 4);
        bq += __shfl_xor_sync(0xffffffffu, bq, 4);
        a  += __shfl_xor_sync(0xffffffffu, a, 8);
        bq += __shfl_xor_sync(0xffffffffu, bq, 8);
        a  += __shfl_xor_sync(0xffffffffu, a, 16);
        bq += __shfl_xor_sync(0xffffffffu, bq, 16);
        if (gid == 0)
            *(float2*)&g_part[half][v * H_OUT + j * 8 + 2 * t4] = make_float2(a, bq);
    }

    // ================= signal done =================
    __threadfence();
    __syncthreads();
    if (tid == 0) atomicAdd(&g_done, 1);
}

// ---------- launch ----------
extern "C" void kernel_launch(void* const* d_in, const int* in_sizes, int n_in,
                              void* d_out, int out_size) {
    const int*   adj = (const int*)d_in[0];       // (1,1024,1024) int32
    const float* X   = (const float*)d_in[1];     // (1,1024,32)
    const float* E   = (const float*)d_in[2];     // (1,1024,1024,8)
    const float* W   = (const float*)d_in[3];     // (72,64)
    const float* b   = (const float*)d_in[4];     // (64,)
    float* out = (float*)d_out;                   // (1,1024,64)

    edge_fused<<<NMAIN + 1, 256>>>(E, adj, W, X, b, out);
}